// round 4
// baseline (speedup 1.0000x reference)
#include <cuda_runtime.h>
#include <cuda_bf16.h>

// x: (256,64,25,3) f32; W_conv: (3,192) f32; W_a: (128,1) f32; out: (256,3,25,25) f32
// Verified math (R1/R3):
//   xbar[n,j] = sum_t x[n,t,j], j=v*3+i (1/64 folded into u)
//   u{1,2}[i,k] = (1/64) sum_c W_conv[i,c*3+k]*W_a[{0,64}+c]
//   s{1,2}[v,k] = sum_i xbar[v*3+i]*u{1,2}[i,k]
//   row (0..74), col q: r=(row%3)*25+q; e = s1[r]+s2[(row/3)*3+(r%3)]
//   E = leaky(e,0.2) = max(e,0.2e); softmax over q. (No exp factorization — leaky is nonlinear.)
// Structure: 2 producer blocks per sample write 75-float partials to scratch;
// last block (atomic ticket) does fold + s/pack + softmax + store. One launch.

#define TPB 320

__device__ float g_scratch[256 * 150];   // [n][half][75]
__device__ int   g_cnt[256];             // zero-init; finisher resets to 0 (replay-safe)

__device__ __forceinline__ unsigned long long add2(unsigned long long a, unsigned long long b) {
    unsigned long long r;
    asm("add.rn.f32x2 %0, %1, %2;" : "=l"(r) : "l"(a), "l"(b));
    return r;
}
__device__ __forceinline__ unsigned long long pack2(float lo, float hi) {
    unsigned long long r;
    asm("mov.b64 %0, {%1, %2};" : "=l"(r) : "f"(lo), "f"(hi));
    return r;
}
__device__ __forceinline__ void unpack2(unsigned long long v, float &lo, float &hi) {
    asm("mov.b64 {%0, %1}, %2;" : "=f"(lo), "=f"(hi) : "l"(v));
}
__device__ __forceinline__ float ex2a(float x) {
    float r; asm("ex2.approx.f32 %0, %1;" : "=f"(r) : "f"(x)); return r;
}
__device__ __forceinline__ float ldcg(const float* p) {
    float r; asm volatile("ld.global.cg.f32 %0, [%1];" : "=f"(r) : "l"(p)); return r;
}

__global__ __launch_bounds__(TPB)
void gat_adj_kernel(const float* __restrict__ x,
                    const float* __restrict__ Wc,
                    const float* __restrict__ Wa,
                    float* __restrict__ out)
{
    __shared__ __align__(16) float buf[1200];          // 16 folded slots x 75 cols
    __shared__ float uu[18];                           // [which*9+i*3+k], /64 folded
    __shared__ float xpart[150];
    __shared__ unsigned long long sp1[75], sp2[75];
    __shared__ int lastFlag;

    const int b    = blockIdx.x;
    const int n    = b >> 1;
    const int half = b & 1;
    const int tid  = threadIdx.x;

    // ---- Phase 1: 32-timestep chunk, 2 LDG.128/thread, in-register pair fold ----
    // f4 index r and r+300: flat 4r+m and 1200+4r+m -> same col (4r+m)%75 (1200%75==0).
    if (tid < 300) {
        const ulonglong2* xg =
            reinterpret_cast<const ulonglong2*>(x) + (size_t)n * 1200 + (size_t)half * 600;
        ulonglong2 a = xg[tid];
        ulonglong2 c = xg[tid + 300];
        ulonglong2 s;
        s.x = add2(a.x, c.x);
        s.y = add2(a.y, c.y);
        reinterpret_cast<ulonglong2*>(buf)[tid] = s;   // buf[slot*75+col]
    } else if (tid < 318) {
        const int idx = tid - 300, which = idx / 9, rem = idx % 9;
        const int i = rem / 3, k = rem % 3;
        float acc = 0.f;
        #pragma unroll 8
        for (int cc = 0; cc < 64; cc++)
            acc += Wc[i * 192 + cc * 3 + k] * Wa[which * 64 + cc];
        uu[idx] = acc * (1.0f / 64.0f);
    }
    __syncthreads();

    // ---- Phase 2: fold 16 slots -> 75 partials, publish to scratch ----
    if (tid < 75) {
        float acc = 0.f;
        #pragma unroll
        for (int i = 0; i < 16; i++) acc += buf[i * 75 + tid];
        g_scratch[n * 150 + half * 75 + tid] = acc;
    }
    __syncthreads();

    // ---- Ticket: last block per sample finishes ----
    if (tid == 0) {
        __threadfence();                                // release our partial
        int old = atomicAdd(&g_cnt[n], 1);
        lastFlag = (old == 1);
        if (old == 1) g_cnt[n] = 0;                     // self-reset for next replay
    }
    __syncthreads();
    if (!lastFlag) return;
    __threadfence();                                    // acquire peers' partials

    // ---- Finish: fold halves ----
    if (tid < 150) xpart[tid] = ldcg(&g_scratch[n * 150 + tid]);
    __syncthreads();

    // ---- s1/s2 (3x3), scale by log2(e), pack with 0.2x ----
    if (tid < 75) {
        const int k  = tid % 3;
        const int v3 = tid - k;
        const float a0 = xpart[v3]     + xpart[75 + v3];
        const float a1 = xpart[v3 + 1] + xpart[75 + v3 + 1];
        const float a2 = xpart[v3 + 2] + xpart[75 + v3 + 2];
        const float L2E = 1.4426950408889634f;
        const float s1 = (a0 * uu[k]     + a1 * uu[3 + k]  + a2 * uu[6 + k])  * L2E;
        const float s2 = (a0 * uu[9 + k] + a1 * uu[12 + k] + a2 * uu[15 + k]) * L2E;
        sp1[tid] = pack2(s1, 0.2f * s1);
        sp2[tid] = pack2(s2, 0.2f * s2);
    }
    __syncthreads();

    // ---- Softmax: 4 threads per row (verified R3 map) ----
    {
        int row = tid >> 2;
        if (row > 74) row = 74;
        const int part = tid & 3;
        const int d  = row % 3;
        const int a3 = row - d;
        const int r0 = d * 25;

        const unsigned long long c0 = sp2[a3];
        const unsigned long long c1 = sp2[a3 + 1];
        const unsigned long long c2 = sp2[a3 + 2];

        const int qs  = (part == 0) ? 0 : part * 6 + 1;   // 0,7,13,19
        const int cnt = (part == 0) ? 7 : 6;

        const int kk0 = (d + qs) % 3;
        unsigned long long ra = (kk0 == 0) ? c0 : ((kk0 == 1) ? c1 : c2);
        unsigned long long rb = (kk0 == 0) ? c1 : ((kk0 == 1) ? c2 : c0);
        unsigned long long rc = (kk0 == 0) ? c2 : ((kk0 == 1) ? c0 : c1);

        float vals[7];
        float sum = 0.f;
        #pragma unroll
        for (int j = 0; j < 7; j++) {
            if (j < cnt) {
                unsigned long long ef = add2(sp1[r0 + qs + j], ra);
                float e, f;
                unpack2(ef, e, f);
                const float vl = ex2a(fmaxf(e, f));
                vals[j] = vl;
                sum += vl;
                unsigned long long t = ra; ra = rb; rb = rc; rc = t;
            }
        }
        sum += __shfl_xor_sync(0xffffffffu, sum, 1);
        sum += __shfl_xor_sync(0xffffffffu, sum, 2);
        const float inv = __fdividef(1.0f, sum);

        if ((tid >> 2) < 75) {
            float* og = out + (size_t)n * 1875 + row * 25 + qs;
            #pragma unroll
            for (int j = 0; j < 7; j++)
                if (j < cnt) og[j] = vals[j] * inv;
        }
    }
}

extern "C" void kernel_launch(void* const* d_in, const int* in_sizes, int n_in,
                              void* d_out, int out_size)
{
    const float* x  = (const float*)d_in[0];
    const float* Wc = (const float*)d_in[1];
    const float* Wa = (const float*)d_in[2];
    float* out = (float*)d_out;
    gat_adj_kernel<<<512, TPB>>>(x, Wc, Wa, out);
}

// round 5
// speedup vs baseline: 1.1860x; 1.1860x over previous
#include <cuda_runtime.h>
#include <cuda_bf16.h>

// x: (256,64,25,3) f32; W_conv: (3,192) f32; W_a: (128,1) f32; out: (256,3,25,25) f32
// Verified math (R1/R3, rel_err ~1e-7):
//   xbar[n,j] = sum_t x[n,t,j], j=v*3+i (1/64 folded into u)
//   u{1,2}[i,k] = (1/64) sum_c W_conv[i,c*3+k]*W_a[{0,64}+c]
//   s{1,2}[v,k] = sum_i xbar[v*3+i]*u{1,2}[i,k]
//   row (0..74), col q: e = s1[(row%3)*25+q] + s2[(row/3)*3 + (row%3+q)%3]
//   E = leaky(e,0.2) = max(e,0.2e)  [NONLINEAR: no exp factorization];  softmax over q.
// Structure: grid=128, 2 samples/block, all 8 LDG.128/thread issued up front,
// double-buffered smem, parallel per-sample phases, 3 barriers total.

#define TPB 320

__device__ __forceinline__ unsigned long long add2(unsigned long long a, unsigned long long b) {
    unsigned long long r;
    asm("add.rn.f32x2 %0, %1, %2;" : "=l"(r) : "l"(a), "l"(b));
    return r;
}
__device__ __forceinline__ unsigned long long pack2(float lo, float hi) {
    unsigned long long r;
    asm("mov.b64 %0, {%1, %2};" : "=l"(r) : "f"(lo), "f"(hi));
    return r;
}
__device__ __forceinline__ void unpack2(unsigned long long v, float &lo, float &hi) {
    asm("mov.b64 {%0, %1}, %2;" : "=f"(lo), "=f"(hi) : "l"(v));
}
__device__ __forceinline__ float ex2a(float x) {
    float r; asm("ex2.approx.f32 %0, %1;" : "=f"(r) : "f"(x)); return r;
}

__global__ __launch_bounds__(TPB)
void gat_adj_kernel(const float* __restrict__ x,
                    const float* __restrict__ Wc,
                    const float* __restrict__ Wa,
                    float* __restrict__ out)
{
    __shared__ __align__(16) float bufA[1200];   // sample0: 16 slots x 75 cols
    __shared__ __align__(16) float bufB[1200];   // sample1
    __shared__ float xbA[75], xbB[75];
    __shared__ float uu[18];
    __shared__ unsigned long long sp1A[75], sp2A[75], sp1B[75], sp2B[75];

    const int n0  = blockIdx.x * 2;
    const int tid = threadIdx.x;

    // ---- Phase 1: issue ALL 8 LDG.128 up front (max MLP), reduce pairs in regs ----
    if (tid < 300) {
        const ulonglong2* xg0 = reinterpret_cast<const ulonglong2*>(x) + (size_t)n0 * 1200;
        const ulonglong2* xg1 = xg0 + 1200;
        ulonglong2 a0 = xg0[tid];
        ulonglong2 b0 = xg0[tid + 300];
        ulonglong2 c0 = xg0[tid + 600];
        ulonglong2 d0 = xg0[tid + 900];
        ulonglong2 a1 = xg1[tid];
        ulonglong2 b1 = xg1[tid + 300];
        ulonglong2 c1 = xg1[tid + 600];
        ulonglong2 d1 = xg1[tid + 900];
        ulonglong2 s0, s1;
        s0.x = add2(add2(a0.x, b0.x), add2(c0.x, d0.x));
        s0.y = add2(add2(a0.y, b0.y), add2(c0.y, d0.y));
        reinterpret_cast<ulonglong2*>(bufA)[tid] = s0;
        s1.x = add2(add2(a1.x, b1.x), add2(c1.x, d1.x));
        s1.y = add2(add2(a1.y, b1.y), add2(c1.y, d1.y));
        reinterpret_cast<ulonglong2*>(bufB)[tid] = s1;
    } else if (tid < 318) {
        const int idx = tid - 300, which = idx / 9, rem = idx % 9;
        const int i = rem / 3, k = rem % 3;
        float acc = 0.f;
        #pragma unroll 8
        for (int cc = 0; cc < 64; cc++)
            acc += Wc[i * 192 + cc * 3 + k] * Wa[which * 64 + cc];
        uu[idx] = acc * (1.0f / 64.0f);
    }
    __syncthreads();

    // ---- Phase 2: fold 16 slots per column — both samples in parallel ----
    if (tid < 75) {
        float acc = 0.f;
        #pragma unroll
        for (int i = 0; i < 16; i++) acc += bufA[i * 75 + tid];
        xbA[tid] = acc;
    } else if (tid >= 160 && tid < 235) {
        const int t = tid - 160;
        float acc = 0.f;
        #pragma unroll
        for (int i = 0; i < 16; i++) acc += bufB[i * 75 + t];
        xbB[t] = acc;
    }
    __syncthreads();

    // ---- Phase 3: s1/s2 (3x3), scale by log2e, pack with 0.2x — both samples ----
    {
        const float L2E = 1.4426950408889634f;
        if (tid < 75) {
            const int k = tid % 3, v3 = tid - k;
            const float a0 = xbA[v3], a1 = xbA[v3 + 1], a2 = xbA[v3 + 2];
            const float s1 = (a0 * uu[k]     + a1 * uu[3 + k]  + a2 * uu[6 + k])  * L2E;
            const float s2 = (a0 * uu[9 + k] + a1 * uu[12 + k] + a2 * uu[15 + k]) * L2E;
            sp1A[tid] = pack2(s1, 0.2f * s1);
            sp2A[tid] = pack2(s2, 0.2f * s2);
        } else if (tid >= 160 && tid < 235) {
            const int t = tid - 160;
            const int k = t % 3, v3 = t - k;
            const float a0 = xbB[v3], a1 = xbB[v3 + 1], a2 = xbB[v3 + 2];
            const float s1 = (a0 * uu[k]     + a1 * uu[3 + k]  + a2 * uu[6 + k])  * L2E;
            const float s2 = (a0 * uu[9 + k] + a1 * uu[12 + k] + a2 * uu[15 + k]) * L2E;
            sp1B[t] = pack2(s1, 0.2f * s1);
            sp2B[t] = pack2(s2, 0.2f * s2);
        }
    }
    __syncthreads();

    // ---- Phase 4: softmax, 2 threads per row, 150 rows (both samples) ----
    {
        int row2 = tid >> 1;
        if (row2 > 149) row2 = 149;               // tid 300..319: safe duplicate work
        const int part = tid & 1;
        const int samp = (row2 >= 75);
        const int row  = row2 - 75 * samp;

        const unsigned long long* sp1 = samp ? sp1B : sp1A;
        const unsigned long long* sp2 = samp ? sp2B : sp2A;

        const int d  = row % 3;
        const int a3 = row - d;
        const int r0 = d * 25;

        const unsigned long long c0 = sp2[a3];
        const unsigned long long c1 = sp2[a3 + 1];
        const unsigned long long c2 = sp2[a3 + 2];

        const int qs  = part ? 13 : 0;
        const int cnt = part ? 12 : 13;

        const int kk0 = (d + qs) % 3;
        unsigned long long ra = (kk0 == 0) ? c0 : ((kk0 == 1) ? c1 : c2);
        unsigned long long rb = (kk0 == 0) ? c1 : ((kk0 == 1) ? c2 : c0);
        unsigned long long rc = (kk0 == 0) ? c2 : ((kk0 == 1) ? c0 : c1);

        float vals[13];
        float sum = 0.f;
        #pragma unroll
        for (int j = 0; j < 13; j++) {
            if (j < cnt) {
                unsigned long long ef = add2(sp1[r0 + qs + j], ra);
                float e, f;
                unpack2(ef, e, f);
                const float vl = ex2a(fmaxf(e, f));
                vals[j] = vl;
                sum += vl;
                unsigned long long t = ra; ra = rb; rb = rc; rc = t;
            }
        }
        sum += __shfl_xor_sync(0xffffffffu, sum, 1);
        const float inv = __fdividef(1.0f, sum);

        if ((tid >> 1) < 150) {
            float* og = out + (size_t)(n0 + samp) * 1875 + row * 25 + qs;
            #pragma unroll
            for (int j = 0; j < 13; j++)
                if (j < cnt) og[j] = vals[j] * inv;
        }
    }
}

extern "C" void kernel_launch(void* const* d_in, const int* in_sizes, int n_in,
                              void* d_out, int out_size)
{
    const float* x  = (const float*)d_in[0];
    const float* Wc = (const float*)d_in[1];
    const float* Wa = (const float*)d_in[2];
    float* out = (float*)d_out;
    gat_adj_kernel<<<128, TPB>>>(x, Wc, Wa, out);
}

// round 6
// speedup vs baseline: 1.5055x; 1.2694x over previous
#include <cuda_runtime.h>
#include <cuda_bf16.h>

// x: (256,64,25,3) f32; W_conv: (3,192) f32; W_a: (128,1) f32; out: (256,3,25,25) f32
// Verified math (R1/R3, rel_err ~1e-7):
//   xbar[n,j] = sum_t x[n,t,j], j=v*3+i (1/64 folded into u)
//   u{1,2}[i,k] = (1/64) sum_c W_conv[i,c*3+k]*W_a[{0,64}+c]
//   s{1,2}[v,k] = sum_i xbar[v*3+i]*u{1,2}[i,k]
//   row (0..74), col q: e = s1[(row%3)*25+q] + s2[(row/3)*3 + ((row%3)+q)%3]
//   E = leaky(e,0.2)=max(e,0.2e) [nonlinear: NO exp factorization]; softmax over q.
// R6: critical-path minimization. All DRAM loads (x AND u inputs) issued at t=0;
// u computed 288-wide with shfl reduction (hidden under x latency); fold+pack
// merged (25 threads); 2 barriers total; direct stores.

#define TPB 320

__device__ __forceinline__ unsigned long long add2(unsigned long long a, unsigned long long b) {
    unsigned long long r;
    asm("add.rn.f32x2 %0, %1, %2;" : "=l"(r) : "l"(a), "l"(b));
    return r;
}
__device__ __forceinline__ unsigned long long pack2(float lo, float hi) {
    unsigned long long r;
    asm("mov.b64 %0, {%1, %2};" : "=l"(r) : "f"(lo), "f"(hi));
    return r;
}
__device__ __forceinline__ void unpack2(unsigned long long v, float &lo, float &hi) {
    asm("mov.b64 {%0, %1}, %2;" : "=f"(lo), "=f"(hi) : "l"(v));
}
__device__ __forceinline__ float ex2a(float x) {
    float r; asm("ex2.approx.f32 %0, %1;" : "=f"(r) : "f"(x)); return r;
}

__global__ __launch_bounds__(TPB)
void gat_adj_kernel(const float* __restrict__ x,
                    const float* __restrict__ Wc,
                    const float* __restrict__ Wa,
                    float* __restrict__ out)
{
    __shared__ __align__(16) float buf[1200];       // 16 partial slots x 75 cols
    __shared__ float uu[18];                        // [which*9+i*3+k], /64 folded
    __shared__ unsigned long long sp1[75], sp2[75]; // packed (s*L2E, 0.2*s*L2E)

    const int n   = blockIdx.x;
    const int tid = threadIdx.x;

    // ---- t=0: issue ALL global loads (x tile + u inputs) concurrently ----
    ulonglong2 xa, xb, xc, xd;
    if (tid < 300) {
        const ulonglong2* xg = reinterpret_cast<const ulonglong2*>(x) + (size_t)n * 1200;
        xa = xg[tid];
        xb = xg[tid + 300];
        xc = xg[tid + 600];
        xd = xg[tid + 900];
    }

    // u inputs: 288 threads, output o=tid/16 (0..17), part p=tid%16, terms c=4p..4p+3
    float wc0, wc1, wc2, wc3;
    float4 wav;
    int o = 0;
    if (tid < 288) {
        o = tid >> 4;
        const int p     = tid & 15;
        const int which = o / 9;
        const int rem   = o % 9;
        const int i     = rem / 3;
        const int k     = rem % 3;
        const int c0    = 4 * p;
        const float* wcb = Wc + i * 192 + k;
        wc0 = wcb[(c0 + 0) * 3];
        wc1 = wcb[(c0 + 1) * 3];
        wc2 = wcb[(c0 + 2) * 3];
        wc3 = wcb[(c0 + 3) * 3];
        wav = reinterpret_cast<const float4*>(Wa + which * 64 + c0)[0];
    }

    // ---- u partials + shfl reduce (runs while x loads are still in flight) ----
    if (tid < 288) {
        float acc = wc0 * wav.x + wc1 * wav.y + wc2 * wav.z + wc3 * wav.w;
        acc += __shfl_xor_sync(0xffffffffu, acc, 1);
        acc += __shfl_xor_sync(0xffffffffu, acc, 2);
        acc += __shfl_xor_sync(0xffffffffu, acc, 4);
        acc += __shfl_xor_sync(0xffffffffu, acc, 8);
        if ((tid & 15) == 0) uu[o] = acc * (1.0f / 64.0f);
    }

    // ---- combine x pairs (f32x2) and stage partial column sums ----
    if (tid < 300) {
        ulonglong2 s;
        s.x = add2(add2(xa.x, xb.x), add2(xc.x, xd.x));
        s.y = add2(add2(xa.y, xb.y), add2(xc.y, xd.y));
        reinterpret_cast<ulonglong2*>(buf)[tid] = s;   // buf[slot*75+col], col=(4*tid+m)%75
    }
    __syncthreads();   // bar 0

    // ---- merged fold + score-pack: thread v (0..24) owns columns 3v..3v+2 ----
    if (tid < 25) {
        const int v3 = tid * 3;
        float a0 = 0.f, a1 = 0.f, a2 = 0.f;
        #pragma unroll
        for (int i = 0; i < 16; i++) {
            const float* row = buf + i * 75 + v3;
            a0 += row[0];
            a1 += row[1];
            a2 += row[2];
        }
        const float L2E = 1.4426950408889634f;
        #pragma unroll
        for (int k = 0; k < 3; k++) {
            const float s1 = (a0 * uu[k]     + a1 * uu[3 + k]  + a2 * uu[6 + k])  * L2E;
            const float s2 = (a0 * uu[9 + k] + a1 * uu[12 + k] + a2 * uu[15 + k]) * L2E;
            sp1[v3 + k] = pack2(s1, 0.2f * s1);
            sp2[v3 + k] = pack2(s2, 0.2f * s2);
        }
    }
    __syncthreads();   // bar 1

    // ---- softmax: 4 threads per row (verified R3 map), direct stores ----
    {
        int row = tid >> 2;
        if (row > 74) row = 74;                 // tid 300..319: safe duplicate work
        const int part = tid & 3;
        const int d  = row % 3;
        const int a3 = row - d;
        const int r0 = d * 25;

        const unsigned long long c0 = sp2[a3];
        const unsigned long long c1 = sp2[a3 + 1];
        const unsigned long long c2 = sp2[a3 + 2];

        const int qs  = (part == 0) ? 0 : part * 6 + 1;   // 0,7,13,19
        const int cnt = (part == 0) ? 7 : 6;

        const int kk0 = (d + qs) % 3;
        unsigned long long ra = (kk0 == 0) ? c0 : ((kk0 == 1) ? c1 : c2);
        unsigned long long rb = (kk0 == 0) ? c1 : ((kk0 == 1) ? c2 : c0);
        unsigned long long rc = (kk0 == 0) ? c2 : ((kk0 == 1) ? c0 : c1);

        float vals[7];
        float sum = 0.f;
        #pragma unroll
        for (int j = 0; j < 7; j++) {
            if (j < cnt) {
                unsigned long long ef = add2(sp1[r0 + qs + j], ra);
                float e, f;
                unpack2(ef, e, f);
                const float vl = ex2a(fmaxf(e, f));
                vals[j] = vl;
                sum += vl;
                unsigned long long t = ra; ra = rb; rb = rc; rc = t;
            }
        }
        sum += __shfl_xor_sync(0xffffffffu, sum, 1);
        sum += __shfl_xor_sync(0xffffffffu, sum, 2);
        const float inv = __fdividef(1.0f, sum);

        if ((tid >> 2) < 75) {
            float* og = out + (size_t)n * 1875 + row * 25 + qs;
            #pragma unroll
            for (int j = 0; j < 7; j++)
                if (j < cnt) og[j] = vals[j] * inv;
        }
    }
}

extern "C" void kernel_launch(void* const* d_in, const int* in_sizes, int n_in,
                              void* d_out, int out_size)
{
    const float* x  = (const float*)d_in[0];
    const float* Wc = (const float*)d_in[1];
    const float* Wa = (const float*)d_in[2];
    float* out = (float*)d_out;
    gat_adj_kernel<<<256, TPB>>>(x, Wc, Wa, out);
}